// round 1
// baseline (speedup 1.0000x reference)
#include <cuda_runtime.h>

// Problem constants
#define Nn 64
#define Cc 64
#define Tt 300
#define Vv 25
#define Dd 64
#define NT (Nn*Tt)        // 19200
#define VC (Vv*Cc)        // 1600
#define VD (Vv*Dd)        // 1600
#define TT1 2             // timesteps per k1 block
#define ROWS1 (TT1*Vv)    // 50
#define TT4 6             // timesteps per k4 block
#define K2_CHUNKS 48
#define BN_EPS 1e-5f

typedef unsigned long long ull;

// Scratch (allocation-free: device globals)
__device__ float g_y[(size_t)NT*VD];   // pre-shift, pre-BN activations
__device__ float g_sum[VD];
__device__ float g_sumsq[VD];
__device__ float g_scale[VD];
__device__ float g_bias[VD];
__device__ int   g_src[VD];
__device__ int   g_soff[VC];           // smem gather offset for shift_in
__device__ float g_maskf[VC];          // tanh(feature_mask)+1

// ---- packed f32x2 helpers (sm_100+) ----
__device__ __forceinline__ ull pack2(float lo, float hi) {
    ull r; asm("mov.b64 %0, {%1,%2};" : "=l"(r) : "f"(lo), "f"(hi)); return r;
}
__device__ __forceinline__ void fma2(ull& d, ull a, ull b) {
    asm("fma.rn.f32x2 %0, %1, %2, %0;" : "+l"(d) : "l"(a), "l"(b));
}
__device__ __forceinline__ float2 unpack2(ull v) {
    float2 f; asm("mov.b64 {%0,%1}, %2;" : "=f"(f.x), "=f"(f.y) : "l"(v)); return f;
}

// ---- prep: mask activation, shift_in offset decode, zero stats ----
__global__ void kprep(const float* __restrict__ fm, const int* __restrict__ shift_in) {
    int j = blockIdx.x * blockDim.x + threadIdx.x;
    if (j < VC) {
        g_maskf[j] = tanhf(fm[j]) + 1.0f;
        int k  = shift_in[j];
        int kv = k / Cc;
        int kc = k - kv * Cc;
        g_soff[j] = kc * ROWS1 + kv;   // offset into xs[c][col] for tl=0
        g_sum[j]   = 0.0f;
        g_sumsq[j] = 0.0f;
    }
}

// ---- k1: gather + mask + GEMM -> y scratch ----
__global__ void __launch_bounds__(256) k1(const float* __restrict__ x0,
                                          const float* __restrict__ W,
                                          const float* __restrict__ b) {
    __shared__ __align__(16) float xs[Cc * ROWS1];   // raw slice   [kc][tl*25+kv]
    __shared__ __align__(16) float xm[Cc * ROWS1];   // gathered    [c][tl*25+v]
    __shared__ __align__(16) float ws[Cc * Dd];      // W row-major

    const int tid = threadIdx.x;
    const int nt0 = blockIdx.x * TT1;
    const int n   = nt0 / Tt;
    const int t0  = nt0 - n * Tt;                    // TT1 divides Tt, never crosses n

    const float* xb = x0 + (size_t)n * Cc * Tt * Vv + (size_t)t0 * Vv;

    // coalesced slice load: xs[kc*50 + (tl*25+kv)] = x0[n, kc, t0+tl, kv]
    for (int i = tid; i < Cc * ROWS1; i += 256) {
        int kc  = i / ROWS1;
        int col = i - kc * ROWS1;
        xs[i] = xb[(size_t)kc * (Tt * Vv) + col];
    }
    for (int i = tid; i < Cc * Dd; i += 256) ws[i] = W[i];
    __syncthreads();

    // gather + mask into transposed tile xm[c][r], r = tl*25 + v
    for (int i = tid; i < Cc * ROWS1; i += 256) {
        int c = i / ROWS1;
        int r = i - c * ROWS1;
        int tl = r / Vv;
        int v  = r - tl * Vv;
        int vc = v * Cc + c;
        xm[i] = xs[g_soff[vc] + tl * Vv] * g_maskf[vc];
    }
    __syncthreads();

    // register-tiled GEMM: 200 threads, each 2 rows x 8 cols, f32x2 packed along d
    if (tid < 200) {
        const int rt = tid >> 3;        // 0..24
        const int dt = tid & 7;         // 0..7
        const int r0 = rt * 2;
        const int d0 = dt * 8;

        ull acc[2][4];
        #pragma unroll
        for (int rr = 0; rr < 2; rr++)
            #pragma unroll
            for (int k = 0; k < 4; k++) acc[rr][k] = 0ull;

        #pragma unroll 8
        for (int c = 0; c < Cc; c++) {
            float2 xp = *(const float2*)&xm[c * ROWS1 + r0];
            ull xa = pack2(xp.x, xp.x);
            ull xc = pack2(xp.y, xp.y);
            const ull* wp = (const ull*)&ws[c * Dd + d0];
            ull w0 = wp[0], w1 = wp[1], w2 = wp[2], w3 = wp[3];
            fma2(acc[0][0], xa, w0); fma2(acc[0][1], xa, w1);
            fma2(acc[0][2], xa, w2); fma2(acc[0][3], xa, w3);
            fma2(acc[1][0], xc, w0); fma2(acc[1][1], xc, w1);
            fma2(acc[1][2], xc, w2); fma2(acc[1][3], xc, w3);
        }

        #pragma unroll
        for (int rr = 0; rr < 2; rr++) {
            int r  = r0 + rr;
            int tl = r / Vv;
            int v  = r - tl * Vv;
            float* yrow = g_y + (size_t)(nt0 + tl) * VD + v * Dd + d0;
            float o[8];
            #pragma unroll
            for (int k = 0; k < 4; k++) {
                float2 f = unpack2(acc[rr][k]);
                o[2*k]   = f.x + b[d0 + 2*k];
                o[2*k+1] = f.y + b[d0 + 2*k + 1];
            }
            *(float4*)(yrow)     = make_float4(o[0], o[1], o[2], o[3]);
            *(float4*)(yrow + 4) = make_float4(o[4], o[5], o[6], o[7]);
        }
    }
}

// ---- k2: per-column sum / sumsq over NT ----
__global__ void __launch_bounds__(256) k2() {
    int col = blockIdx.x * 256 + threadIdx.x;
    if (col >= VD) return;
    const int rows = NT / K2_CHUNKS;          // 400
    const size_t r0 = (size_t)blockIdx.y * rows;
    const float* p = g_y + r0 * VD + col;
    float s = 0.0f, ss = 0.0f;
    #pragma unroll 4
    for (int r = 0; r < rows; r++) {
        float v = p[(size_t)r * VD];
        s += v;
        ss += v * v;
    }
    atomicAdd(&g_sum[col], s);
    atomicAdd(&g_sumsq[col], ss);
}

// ---- k3: fold mean/var/gamma/beta/shift_out into per-column affine ----
__global__ void k3(const float* __restrict__ gamma, const float* __restrict__ beta,
                   const int* __restrict__ shift_out) {
    int j = blockIdx.x * blockDim.x + threadIdx.x;
    if (j >= VD) return;
    int src = shift_out[j];
    const float inv_n = 1.0f / (float)NT;
    float mean = g_sum[src] * inv_n;
    float var  = g_sumsq[src] * inv_n - mean * mean;
    float sc   = gamma[j] * rsqrtf(var + BN_EPS);
    g_scale[j] = sc;
    g_bias[j]  = beta[j] - mean * sc;
    g_src[j]   = src;
}

// ---- k4: gather + affine + residual + relu, write (N,D,T,V) ----
__global__ void __launch_bounds__(256) k4(const float* __restrict__ x0,
                                          float* __restrict__ out) {
    __shared__ float ysm[TT4 * VD];            // 9600 floats
    const int n  = blockIdx.x;
    const int t0 = blockIdx.y * TT4;
    const int nt0 = n * Tt + t0;

    const float* ysrc = g_y + (size_t)nt0 * VD;
    for (int i = threadIdx.x; i < TT4 * VD; i += 256) ysm[i] = ysrc[i];
    __syncthreads();

    const size_t base = (size_t)n * Dd * Tt * Vv + (size_t)t0 * Vv;
    const int tot = Dd * TT4 * Vv;             // 9600
    for (int e = threadIdx.x; e < tot; e += 256) {
        int v  = e % Vv;
        int q  = e / Vv;
        int tl = q % TT4;
        int d  = q / TT4;
        int j  = v * Dd + d;
        float val = ysm[tl * VD + g_src[j]] * g_scale[j] + g_bias[j];
        size_t a = base + (size_t)d * (Tt * Vv) + tl * Vv + v;
        val += x0[a];
        out[a] = fmaxf(val, 0.0f);
    }
}

extern "C" void kernel_launch(void* const* d_in, const int* in_sizes, int n_in,
                              void* d_out, int out_size) {
    const float* x0        = (const float*)d_in[0];
    const float* fm        = (const float*)d_in[1];
    const float* W         = (const float*)d_in[2];
    const float* b         = (const float*)d_in[3];
    const float* gamma     = (const float*)d_in[4];
    const float* beta      = (const float*)d_in[5];
    const int*   shift_in  = (const int*)d_in[6];
    const int*   shift_out = (const int*)d_in[7];
    float* out = (float*)d_out;

    kprep<<<(VC + 255) / 256, 256>>>(fm, shift_in);
    k1<<<NT / TT1, 256>>>(x0, W, b);
    k2<<<dim3((VD + 255) / 256, K2_CHUNKS), 256>>>();
    k3<<<(VD + 255) / 256, 256>>>(gamma, beta, shift_out);
    k4<<<dim3(Nn, Tt / TT4), 256>>>(x0, out);
}

// round 2
// speedup vs baseline: 1.2037x; 1.2037x over previous
#include <cuda_runtime.h>

#define Nn 64
#define Cc 64
#define Tt 300
#define Vv 25
#define Dd 64
#define NT (Nn*Tt)        // 19200
#define VC (Vv*Cc)        // 1600
#define VD (Vv*Dd)        // 1600
#define TT1 6
#define R1 (TT1*Vv)       // 150 rows per k1 block
#define TT4 10
#define NSLOT 32
#define BN_EPS 1e-5f

typedef unsigned long long ull;

// Scratch (allocation-free: device globals)
__device__ float g_y[(size_t)NT*VD];       // pre-shift, pre-BN activations
__device__ float g_psum[NSLOT][VD];
__device__ float g_psq[NSLOT][VD];
__device__ float g_scale[VD];
__device__ float g_bias[VD];
__device__ int   g_src[VD];
__device__ int   g_soff[VC];               // smem gather offset for shift_in
__device__ float g_maskf[VC];              // tanh(feature_mask)+1

// ---- packed f32x2 helpers (sm_100+) ----
__device__ __forceinline__ ull pack2s(float x) {
    ull r; asm("mov.b64 %0, {%1,%1};" : "=l"(r) : "f"(x)); return r;
}
__device__ __forceinline__ void fma2(ull& d, ull a, ull b) {
    asm("fma.rn.f32x2 %0, %1, %2, %0;" : "+l"(d) : "l"(a), "l"(b));
}
__device__ __forceinline__ float2 unpack2(ull v) {
    float2 f; asm("mov.b64 {%0,%1}, %2;" : "=f"(f.x), "=f"(f.y) : "l"(v)); return f;
}

// ---- prep: mask activation, shift_in offset decode, zero stat slots ----
__global__ void kprep(const float* __restrict__ fm, const int* __restrict__ shift_in) {
    int idx = blockIdx.x * blockDim.x + threadIdx.x;
    if (idx < NSLOT * VD) {
        (&g_psum[0][0])[idx] = 0.0f;
        (&g_psq[0][0])[idx]  = 0.0f;
    }
    if (idx < VC) {
        g_maskf[idx] = tanhf(fm[idx]) + 1.0f;
        int k  = shift_in[idx];
        int kv = k / Cc;
        int kc = k - kv * Cc;
        g_soff[idx] = kc * R1 + kv;   // offset into xs for tl=0
    }
}

// ---- k1: inline gather + mask + GEMM + bias + fused column stats -> y ----
__global__ void __launch_bounds__(256, 2) k1(const float* __restrict__ x0,
                                             const float* __restrict__ W,
                                             const float* __restrict__ b) {
    extern __shared__ float sm[];
    float* xs  = sm;                      // Cc*R1 = 9600 floats: [kc][tl*25+kv]
    float* ws  = xs + Cc * R1;            // 4096: W row-major
    float* msk = ws + Cc * Dd;            // 1600
    int*   sof = (int*)(msk + VC);        // 1600

    const int tid = threadIdx.x;
    const int nt0 = blockIdx.x * TT1;
    const int n   = nt0 / Tt;
    const int t0  = nt0 - n * Tt;         // TT1 | Tt, never crosses n

    const float* xb = x0 + (size_t)n * Cc * Tt * Vv + (size_t)t0 * Vv;

    // coalesced slice load: xs[kc*150 + (tl*25+kv)] = x0[n, kc, t0+tl, kv]
    for (int i = tid; i < Cc * R1; i += 256) {
        int kc  = i / R1;
        int col = i - kc * R1;
        xs[i] = xb[(size_t)kc * (Tt * Vv) + col];
    }
    for (int i = tid; i < Cc * Dd; i += 256) ws[i] = W[i];
    for (int i = tid; i < VC; i += 256) { msk[i] = g_maskf[i]; sof[i] = g_soff[i]; }
    __syncthreads();

    // 200 threads: thread (v, dt) computes rows r=v*6+tl (tl=0..5), cols d0..d0+7
    if (tid < 200) {
        const int v  = tid >> 3;          // 0..24
        const int dt = tid & 7;           // 0..7
        const int d0 = dt * 8;

        ull acc[TT1][4];
        #pragma unroll
        for (int tl = 0; tl < TT1; tl++)
            #pragma unroll
            for (int k = 0; k < 4; k++) acc[tl][k] = 0ull;

        #pragma unroll 2
        for (int c = 0; c < Cc; c++) {
            const int   base = sof[v * Cc + c];
            const float m    = msk[v * Cc + c];
            const ull* wp = (const ull*)&ws[c * Dd + d0];
            ull w0 = wp[0], w1 = wp[1], w2 = wp[2], w3 = wp[3];
            #pragma unroll
            for (int tl = 0; tl < TT1; tl++) {
                float xv = xs[base + tl * Vv] * m;
                ull xa = pack2s(xv);
                fma2(acc[tl][0], xa, w0);
                fma2(acc[tl][1], xa, w1);
                fma2(acc[tl][2], xa, w2);
                fma2(acc[tl][3], xa, w3);
            }
        }

        float bs[8];
        #pragma unroll
        for (int k = 0; k < 8; k++) bs[k] = b[d0 + k];

        float s[8], q[8];
        #pragma unroll
        for (int k = 0; k < 8; k++) { s[k] = 0.0f; q[k] = 0.0f; }

        #pragma unroll
        for (int tl = 0; tl < TT1; tl++) {
            float o[8];
            #pragma unroll
            for (int k = 0; k < 4; k++) {
                float2 f = unpack2(acc[tl][k]);
                o[2*k]   = f.x + bs[2*k];
                o[2*k+1] = f.y + bs[2*k+1];
            }
            float* yr = g_y + (size_t)(nt0 + tl) * VD + v * Dd + d0;
            *(float4*)(yr)     = make_float4(o[0], o[1], o[2], o[3]);
            *(float4*)(yr + 4) = make_float4(o[4], o[5], o[6], o[7]);
            #pragma unroll
            for (int k = 0; k < 8; k++) { s[k] += o[k]; q[k] += o[k] * o[k]; }
        }

        const int slot = blockIdx.x & (NSLOT - 1);
        const int colb = v * Dd + d0;
        #pragma unroll
        for (int k = 0; k < 8; k++) {
            atomicAdd(&g_psum[slot][colb + k], s[k]);
            atomicAdd(&g_psq[slot][colb + k],  q[k]);
        }
    }
}

// ---- k3: reduce slots at src column, fold shift_out/gamma/beta -> affine ----
__global__ void k3(const float* __restrict__ gamma, const float* __restrict__ beta,
                   const int* __restrict__ shift_out) {
    int j = blockIdx.x * blockDim.x + threadIdx.x;
    if (j >= VD) return;
    const int src = shift_out[j];
    float s = 0.0f, q = 0.0f;
    #pragma unroll
    for (int sl = 0; sl < NSLOT; sl++) { s += g_psum[sl][src]; q += g_psq[sl][src]; }
    const float inv_n = 1.0f / (float)NT;
    float mean = s * inv_n;
    float var  = q * inv_n - mean * mean;
    float sc   = gamma[j] * rsqrtf(var + BN_EPS);
    g_scale[j] = sc;
    g_bias[j]  = beta[j] - mean * sc;
    g_src[j]   = src;
}

// ---- k4: gather + affine + residual + relu, write (N,D,T,V) ----
__global__ void __launch_bounds__(256) k4(const float* __restrict__ x0,
                                          float* __restrict__ out) {
    extern __shared__ float sm4[];
    float* ysm = sm4;                    // TT4*VD = 16000
    float* scl = ysm + TT4 * VD;         // 1600
    float* bia = scl + VD;               // 1600
    int*   src = (int*)(bia + VD);       // 1600

    const int n   = blockIdx.x;
    const int t0  = blockIdx.y * TT4;
    const int nt0 = n * Tt + t0;

    const float* ysrc = g_y + (size_t)nt0 * VD;
    for (int i = threadIdx.x; i < TT4 * VD; i += 256) ysm[i] = ysrc[i];
    for (int i = threadIdx.x; i < VD; i += 256) {
        scl[i] = g_scale[i]; bia[i] = g_bias[i]; src[i] = g_src[i];
    }
    __syncthreads();

    const size_t base = (size_t)n * Dd * Tt * Vv + (size_t)t0 * Vv;
    const int tot = Dd * TT4 * Vv;       // 16000
    for (int e = threadIdx.x; e < tot; e += 256) {
        int v  = e % Vv;
        int qd = e / Vv;
        int tl = qd % TT4;
        int d  = qd / TT4;
        int j  = v * Dd + d;
        float val = ysm[tl * VD + src[j]] * scl[j] + bia[j];
        size_t a = base + (size_t)d * (Tt * Vv) + tl * Vv + v;
        val += x0[a];
        out[a] = fmaxf(val, 0.0f);
    }
}

extern "C" void kernel_launch(void* const* d_in, const int* in_sizes, int n_in,
                              void* d_out, int out_size) {
    const float* x0        = (const float*)d_in[0];
    const float* fm        = (const float*)d_in[1];
    const float* W         = (const float*)d_in[2];
    const float* b         = (const float*)d_in[3];
    const float* gamma     = (const float*)d_in[4];
    const float* beta      = (const float*)d_in[5];
    const int*   shift_in  = (const int*)d_in[6];
    const int*   shift_out = (const int*)d_in[7];
    float* out = (float*)d_out;

    const int smem1 = (Cc * R1 + Cc * Dd + VC) * 4 + VC * 4;       // 67584 B
    const int smem4 = (TT4 * VD + 2 * VD) * 4 + VD * 4;            // 83200 B
    cudaFuncSetAttribute(k1, cudaFuncAttributeMaxDynamicSharedMemorySize, smem1);
    cudaFuncSetAttribute(k4, cudaFuncAttributeMaxDynamicSharedMemorySize, smem4);

    kprep<<<(NSLOT * VD + 255) / 256, 256>>>(fm, shift_in);
    k1<<<NT / TT1, 256, smem1>>>(x0, W, b);
    k3<<<(VD + 255) / 256, 256>>>(gamma, beta, shift_out);
    k4<<<dim3(Nn, Tt / TT4), 256, smem4>>>(x0, out);
}

// round 3
// speedup vs baseline: 2.3001x; 1.9109x over previous
#include <cuda_runtime.h>

#define Nn 64
#define Cc 64
#define Tt 300
#define Vv 25
#define Dd 64
#define NT (Nn*Tt)        // 19200
#define VC (Vv*Cc)        // 1600
#define VD (Vv*Dd)        // 1600
#define TT1 6
#define R1 (TT1*Vv)       // 150 rows per k1 block
#define TT4 4
#define YS 1624           // padded y row stride in k4 smem (floats)
#define TBS 67            // table stride per v (float4 units)
#define NSLOT 32
#define BN_EPS 1e-5f

typedef unsigned long long ull;

// Scratch (allocation-free: device globals)
__device__ float  g_y[(size_t)NT*VD];     // pre-shift, pre-BN activations
__device__ float  g_psum[NSLOT][VD];
__device__ float  g_psq[NSLOT][VD];
__device__ float4 g_tab4[Vv*TBS];         // (scale, bias, padded_src_bits, 0) at v*67+d
__device__ float2 g_ms2[VC];              // (tanh(mask)+1, soff_bits)

// ---- packed f32x2 helpers (sm_100+) ----
__device__ __forceinline__ ull pack2s(float x) {
    ull r; asm("mov.b64 %0, {%1,%1};" : "=l"(r) : "f"(x)); return r;
}
__device__ __forceinline__ void fma2(ull& d, ull a, ull b) {
    asm("fma.rn.f32x2 %0, %1, %2, %0;" : "+l"(d) : "l"(a), "l"(b));
}
__device__ __forceinline__ float2 unpack2(ull v) {
    float2 f; asm("mov.b64 {%0,%1}, %2;" : "=f"(f.x), "=f"(f.y) : "l"(v)); return f;
}

// ---- prep: mask activation + shift_in offset decode (packed), zero stats ----
__global__ void kprep(const float* __restrict__ fm, const int* __restrict__ shift_in) {
    int idx = blockIdx.x * blockDim.x + threadIdx.x;
    if (idx < NSLOT * VD) {
        (&g_psum[0][0])[idx] = 0.0f;
        (&g_psq[0][0])[idx]  = 0.0f;
    }
    if (idx < VC) {
        int k  = shift_in[idx];
        int kv = k / Cc;
        int kc = k - kv * Cc;
        g_ms2[idx] = make_float2(tanhf(fm[idx]) + 1.0f,
                                 __int_as_float(kc * R1 + kv));
    }
}

// ---- k1: inline gather + mask + GEMM + bias + fused column stats -> y ----
__global__ void __launch_bounds__(256, 3) k1(const float* __restrict__ x0,
                                             const float* __restrict__ W,
                                             const float* __restrict__ b) {
    extern __shared__ float sm[];
    float*  xs  = sm;                       // Cc*R1 = 9600 floats: [kc][tl*25+kv]
    float*  ws  = xs + Cc * R1;             // 4096 floats: W row-major
    float2* ms2 = (float2*)(ws + Cc * Dd);  // 1600 float2

    const int tid = threadIdx.x;
    const int nt0 = blockIdx.x * TT1;
    const int n   = nt0 / Tt;
    const int t0  = nt0 - n * Tt;           // TT1 | Tt, never crosses n

    const float* xb = x0 + (size_t)n * Cc * Tt * Vv + (size_t)t0 * Vv;

    // coalesced slice load: xs[kc*150 + (tl*25+kv)] = x0[n, kc, t0+tl, kv]
    for (int i = tid; i < Cc * R1; i += 256) {
        int kc  = i / R1;
        int col = i - kc * R1;
        xs[i] = xb[(size_t)kc * (Tt * Vv) + col];
    }
    for (int i = tid; i < Cc * Dd; i += 256) ws[i] = W[i];
    for (int i = tid; i < VC; i += 256) ms2[i] = g_ms2[i];
    __syncthreads();

    // 200 threads: thread (v, dt) computes rows r=v*6+tl (tl=0..5), cols d0..d0+7
    if (tid < 200) {
        const int v  = tid >> 3;            // 0..24
        const int dt = tid & 7;             // 0..7
        const int d0 = dt * 8;

        ull acc[TT1][4];
        #pragma unroll
        for (int tl = 0; tl < TT1; tl++)
            #pragma unroll
            for (int k = 0; k < 4; k++) acc[tl][k] = 0ull;

        const float2* msp = ms2 + v * Cc;

        #pragma unroll 2
        for (int c = 0; c < Cc; c++) {
            float2 mo = msp[c];
            const int   base = __float_as_int(mo.y);
            const float m    = mo.x;
            const ulonglong2* wp = (const ulonglong2*)(ws + c * Dd + d0);
            ulonglong2 wA = wp[0];
            ulonglong2 wB = wp[1];
            float xv[TT1];
            #pragma unroll
            for (int tl = 0; tl < TT1; tl++) xv[tl] = xs[base + tl * Vv] * m;
            #pragma unroll
            for (int tl = 0; tl < TT1; tl++) {
                ull xa = pack2s(xv[tl]);
                fma2(acc[tl][0], xa, wA.x);
                fma2(acc[tl][1], xa, wA.y);
                fma2(acc[tl][2], xa, wB.x);
                fma2(acc[tl][3], xa, wB.y);
            }
        }

        float bs[8];
        #pragma unroll
        for (int k = 0; k < 8; k++) bs[k] = b[d0 + k];

        float s[8], q[8];
        #pragma unroll
        for (int k = 0; k < 8; k++) { s[k] = 0.0f; q[k] = 0.0f; }

        #pragma unroll
        for (int tl = 0; tl < TT1; tl++) {
            float o[8];
            #pragma unroll
            for (int k = 0; k < 4; k++) {
                float2 f = unpack2(acc[tl][k]);
                o[2*k]   = f.x + bs[2*k];
                o[2*k+1] = f.y + bs[2*k+1];
            }
            float* yr = g_y + (size_t)(nt0 + tl) * VD + v * Dd + d0;
            *(float4*)(yr)     = make_float4(o[0], o[1], o[2], o[3]);
            *(float4*)(yr + 4) = make_float4(o[4], o[5], o[6], o[7]);
            #pragma unroll
            for (int k = 0; k < 8; k++) { s[k] += o[k]; q[k] += o[k] * o[k]; }
        }

        const int slot = blockIdx.x & (NSLOT - 1);
        const int colb = v * Dd + d0;
        #pragma unroll
        for (int k = 0; k < 8; k++) {
            atomicAdd(&g_psum[slot][colb + k], s[k]);
            atomicAdd(&g_psq[slot][colb + k],  q[k]);
        }
    }
}

// ---- k3: reduce slots at src column, fold shift_out/gamma/beta -> fused table ----
__global__ void k3(const float* __restrict__ gamma, const float* __restrict__ beta,
                   const int* __restrict__ shift_out) {
    int j = blockIdx.x * blockDim.x + threadIdx.x;
    if (j >= VD) return;
    const int src = shift_out[j];
    float s = 0.0f, q = 0.0f;
    #pragma unroll
    for (int sl = 0; sl < NSLOT; sl++) { s += g_psum[sl][src]; q += g_psq[sl][src]; }
    const float inv_n = 1.0f / (float)NT;
    float mean = s * inv_n;
    float var  = q * inv_n - mean * mean;
    float sc   = gamma[j] * rsqrtf(var + BN_EPS);
    int v = j / Dd;
    int d = j - v * Dd;
    int psrc = src + (src >> 6);            // padded column index for k4 smem
    g_tab4[v * TBS + d] = make_float4(sc, beta[j] - mean * sc,
                                      __int_as_float(psrc), 0.0f);
}

// ---- k4: padded-smem gather + affine + residual + relu, write (N,D,T,V) ----
__global__ void __launch_bounds__(256) k4(const float* __restrict__ x0,
                                          float* __restrict__ out) {
    extern __shared__ float sm4[];
    float*  ysm = sm4;                       // TT4*YS = 6496 floats (padded)
    float4* tb4 = (float4*)(ysm + TT4 * YS); // Vv*TBS = 1675 float4

    const int tid = threadIdx.x;
    const int n   = blockIdx.x;
    const int t0  = blockIdx.y * TT4;
    const int nt0 = n * Tt + t0;

    // stage fused table
    for (int i = tid; i < Vv * TBS; i += 256) tb4[i] = g_tab4[i];

    // stage y rows with per-v padding: pc = col + col/64
    #pragma unroll
    for (int tl = 0; tl < TT4; tl++) {
        const float* yr = g_y + (size_t)(nt0 + tl) * VD;
        for (int col = tid; col < VD; col += 256)
            ysm[tl * YS + col + (col >> 6)] = yr[col];
    }
    __syncthreads();

    const size_t base = (size_t)n * Dd * Tt * Vv + (size_t)t0 * Vv;
    const float* xp = x0 + base;
    float* op = out + base;

    // 6400 elements, exactly 25 iterations of 256 threads
    #pragma unroll 5
    for (int it = 0; it < 25; it++) {
        int e  = tid + it * 256;
        int qd = e / 25;
        int v  = e - qd * 25;
        int tl = qd & (TT4 - 1);
        int d  = qd >> 2;
        float4 t = tb4[v * TBS + d];
        float val = ysm[tl * YS + __float_as_int(t.z)] * t.x + t.y;
        size_t a = (size_t)d * (Tt * Vv) + tl * Vv + v;
        val += xp[a];
        op[a] = fmaxf(val, 0.0f);
    }
}

extern "C" void kernel_launch(void* const* d_in, const int* in_sizes, int n_in,
                              void* d_out, int out_size) {
    const float* x0        = (const float*)d_in[0];
    const float* fm        = (const float*)d_in[1];
    const float* W         = (const float*)d_in[2];
    const float* b         = (const float*)d_in[3];
    const float* gamma     = (const float*)d_in[4];
    const float* beta      = (const float*)d_in[5];
    const int*   shift_in  = (const int*)d_in[6];
    const int*   shift_out = (const int*)d_in[7];
    float* out = (float*)d_out;

    const int smem1 = (Cc * R1 + Cc * Dd) * 4 + VC * 8;           // 67584 B
    const int smem4 = TT4 * YS * 4 + Vv * TBS * 16;               // 52784 B
    cudaFuncSetAttribute(k1, cudaFuncAttributeMaxDynamicSharedMemorySize, smem1);
    cudaFuncSetAttribute(k4, cudaFuncAttributeMaxDynamicSharedMemorySize, smem4);

    kprep<<<(NSLOT * VD + 255) / 256, 256>>>(fm, shift_in);
    k1<<<NT / TT1, 256, smem1>>>(x0, W, b);
    k3<<<(VD + 255) / 256, 256>>>(gamma, beta, shift_out);
    k4<<<dim3(Nn, Tt / TT4), 256, smem4>>>(x0, out);
}

// round 4
// speedup vs baseline: 2.6121x; 1.1356x over previous
#include <cuda_runtime.h>

#define Nn 64
#define Cc 64
#define Tt 300
#define Vv 25
#define Dd 64
#define NT (Nn*Tt)        // 19200
#define VC (Vv*Cc)        // 1600
#define VD (Vv*Dd)        // 1600
#define TT1 6
#define R1 (TT1*Vv)       // 150 rows per k1 block
#define YSTR 151          // padded d-row stride in k1 staging smem
#define TV (Tt*Vv)        // 7500 floats per (n,d) plane
#define NSLOT 32
#define BN_EPS 1e-5f

typedef unsigned long long ull;

// Scratch (allocation-free: device globals)
__device__ float          g_y[(size_t)NT*VD];  // y in final (N,D,T,V) layout, pre-BN
__device__ float          g_psum[NSLOT][VD];
__device__ float          g_psq[NSLOT][VD];
__device__ float          g_sclt[Dd*Vv];       // scale indexed [d*25+v] (output col)
__device__ float          g_biat[Dd*Vv];       // bias  indexed [d*25+v]
__device__ float2         g_ms2[VC];           // [c*25+v] = (tanh(mask)+1, soff_bits)
__device__ unsigned short g_srco[Dd*Vv];       // [d*25+vout] = d_src*151 + v_src

// ---- packed f32x2 helpers (sm_100+) ----
__device__ __forceinline__ ull pack2s(float x) {
    ull r; asm("mov.b64 %0, {%1,%1};" : "=l"(r) : "f"(x)); return r;
}
__device__ __forceinline__ void fma2(ull& d, ull a, ull b) {
    asm("fma.rn.f32x2 %0, %1, %2, %0;" : "+l"(d) : "l"(a), "l"(b));
}
__device__ __forceinline__ float2 unpack2(ull v) {
    float2 f; asm("mov.b64 {%0,%1}, %2;" : "=f"(f.x), "=f"(f.y) : "l"(v)); return f;
}

// ---- prep: tables + zero stats ----
__global__ void kprep(const float* __restrict__ fm,
                      const int* __restrict__ shift_in,
                      const int* __restrict__ shift_out) {
    int idx = blockIdx.x * blockDim.x + threadIdx.x;
    if (idx < NSLOT * VD) {
        (&g_psum[0][0])[idx] = 0.0f;
        (&g_psq[0][0])[idx]  = 0.0f;
    }
    if (idx < VC) {
        int v = idx >> 6, c = idx & 63;
        int k  = shift_in[idx];
        int kv = k >> 6, kc = k & 63;
        g_ms2[c * Vv + v] = make_float2(tanhf(fm[idx]) + 1.0f,
                                        __int_as_float(kc * R1 + kv));
        int so = shift_out[idx];                 // src col for output (v, d=c)
        int vs = so >> 6, ds = so & 63;
        g_srco[c * Vv + v] = (unsigned short)(ds * YSTR + vs);
    }
}

// ---- k1: gather+mask+GEMM+bias+stats, staged transposed+shift_out write ----
__global__ void __launch_bounds__(256, 3) k1(const float* __restrict__ x0,
                                             const float* __restrict__ W,
                                             const float* __restrict__ b) {
    extern __shared__ float sm[];
    float*  xs   = sm;                              // union: xs[64][150] / ys[64][151]
    float*  ys   = sm;                              // 9664 floats
    float*  ws   = sm + Dd * YSTR;                  // 4096 floats: W row-major
    float2* ms2  = (float2*)(ws + Cc * Dd);         // 1600 float2, [c*25+v]
    unsigned short* sro = (unsigned short*)(ms2 + VC);  // 1600 u16, [d*25+v]

    const int tid = threadIdx.x;
    const int nt0 = blockIdx.x * TT1;
    const int n   = nt0 / Tt;
    const int t0  = nt0 - n * Tt;                   // TT1 | Tt

    const float* xb = x0 + (size_t)n * Cc * TV + (size_t)t0 * Vv;

    // coalesced slice load: xs[kc*150 + (tl*25+kv)] = x0[n, kc, t0+tl, kv]
    for (int i = tid; i < Cc * R1; i += 256) {
        int kc  = i / R1;
        int col = i - kc * R1;
        xs[i] = xb[(size_t)kc * TV + col];
    }
    for (int i = tid; i < Cc * Dd; i += 256) ws[i] = W[i];
    for (int i = tid; i < VC; i += 256) { ms2[i] = g_ms2[i]; sro[i] = g_srco[i]; }
    __syncthreads();

    // 200 threads: thread (dt, v), v fastest: rows (v, tl), cols d0..d0+7
    float o[TT1][8];
    const int v  = tid % Vv;
    const int dt = tid / Vv;            // 0..7 valid, dt>=8 idle
    const int d0 = dt * 8;

    if (dt < 8) {
        ull acc[TT1][4];
        #pragma unroll
        for (int tl = 0; tl < TT1; tl++)
            #pragma unroll
            for (int k = 0; k < 4; k++) acc[tl][k] = 0ull;

        #pragma unroll 2
        for (int c = 0; c < Cc; c++) {
            float2 mo = ms2[c * Vv + v];
            const int   base = __float_as_int(mo.y);
            const float m    = mo.x;
            const ulonglong2* wp = (const ulonglong2*)(ws + c * Dd + d0);
            ulonglong2 wA = wp[0];
            ulonglong2 wB = wp[1];
            float xv[TT1];
            #pragma unroll
            for (int tl = 0; tl < TT1; tl++) xv[tl] = xs[base + tl * Vv] * m;
            #pragma unroll
            for (int tl = 0; tl < TT1; tl++) {
                ull xa = pack2s(xv[tl]);
                fma2(acc[tl][0], xa, wA.x);
                fma2(acc[tl][1], xa, wA.y);
                fma2(acc[tl][2], xa, wB.x);
                fma2(acc[tl][3], xa, wB.y);
            }
        }

        float bs[8];
        #pragma unroll
        for (int k = 0; k < 8; k++) bs[k] = b[d0 + k];

        float s[8], q[8];
        #pragma unroll
        for (int k = 0; k < 8; k++) { s[k] = 0.0f; q[k] = 0.0f; }

        #pragma unroll
        for (int tl = 0; tl < TT1; tl++) {
            #pragma unroll
            for (int k = 0; k < 4; k++) {
                float2 f = unpack2(acc[tl][k]);
                o[tl][2*k]   = f.x + bs[2*k];
                o[tl][2*k+1] = f.y + bs[2*k+1];
            }
            #pragma unroll
            for (int k = 0; k < 8; k++) { s[k] += o[tl][k]; q[k] += o[tl][k] * o[tl][k]; }
        }

        const int slot = blockIdx.x & (NSLOT - 1);
        const int colb = v * Dd + d0;               // pre-shift (source) column
        #pragma unroll
        for (int k = 0; k < 8; k++) {
            atomicAdd(&g_psum[slot][colb + k], s[k]);
            atomicAdd(&g_psq[slot][colb + k],  q[k]);
        }
    }

    __syncthreads();   // all xs reads done; reuse region as ys

    if (dt < 8) {
        #pragma unroll
        for (int k = 0; k < 8; k++) {
            #pragma unroll
            for (int tl = 0; tl < TT1; tl++)
                ys[(d0 + k) * YSTR + tl * Vv + v] = o[tl][k];
        }
    }
    __syncthreads();

    // cooperative shift_out-gathered, transposed global write:
    // y[n][d][t0+tl][vout], 150-float contiguous runs per d
    float* yb = g_y + ((size_t)n * Dd) * TV + t0 * Vv;
    for (int i = tid; i < Dd * R1; i += 256) {
        int d = i / R1;
        int r = i - d * R1;                          // tl*25 + vout
        int tl = r / Vv;
        int vo = r - tl * Vv;
        float val = ys[tl * Vv + (int)sro[d * Vv + vo]];
        yb[(size_t)d * TV + r] = val;
    }
}

// ---- k3: reduce slots at src column, fold shift_out/gamma/beta -> tables ----
__global__ void k3(const float* __restrict__ gamma, const float* __restrict__ beta,
                   const int* __restrict__ shift_out) {
    int j = blockIdx.x * blockDim.x + threadIdx.x;
    if (j >= VD) return;
    const int src = shift_out[j];
    float s = 0.0f, q = 0.0f;
    #pragma unroll
    for (int sl = 0; sl < NSLOT; sl++) { s += g_psum[sl][src]; q += g_psq[sl][src]; }
    const float inv_n = 1.0f / (float)NT;
    float mean = s * inv_n;
    float var  = q * inv_n - mean * mean;
    float sc   = gamma[j] * rsqrtf(var + BN_EPS);
    int v = j >> 6, d = j & 63;
    g_sclt[d * Vv + v] = sc;
    g_biat[d * Vv + v] = beta[j] - mean * sc;
}

// ---- k4: pure streaming affine + residual + relu over (n,d) planes ----
__global__ void __launch_bounds__(256) k4(const float* __restrict__ x0,
                                          float* __restrict__ out) {
    __shared__ float4 s4[Vv], b4[Vv];
    const int tid = threadIdx.x;
    const int d = blockIdx.x & 63;

    if (tid < Vv) {
        int m = tid;
        const float* sp = g_sclt + d * Vv;
        const float* bp = g_biat + d * Vv;
        int v0 = (4*m) % 25, v1 = (4*m+1) % 25, v2 = (4*m+2) % 25, v3 = (4*m+3) % 25;
        s4[m] = make_float4(sp[v0], sp[v1], sp[v2], sp[v3]);
        b4[m] = make_float4(bp[v0], bp[v1], bp[v2], bp[v3]);
    }
    __syncthreads();

    const size_t base = (size_t)blockIdx.x * TV;     // (n*64+d)*7500
    const float4* yp = (const float4*)(g_y + base);
    const float4* xp = (const float4*)(x0 + base);
    float4* op = (float4*)(out + base);

    #pragma unroll 2
    for (int i = tid; i < TV / 4; i += 256) {        // 1875 float4
        int m = i % 25;
        float4 y = yp[i];
        float4 x = xp[i];
        float4 s = s4[m];
        float4 bb = b4[m];
        float4 r;
        r.x = fmaxf(fmaf(y.x, s.x, bb.x) + x.x, 0.0f);
        r.y = fmaxf(fmaf(y.y, s.y, bb.y) + x.y, 0.0f);
        r.z = fmaxf(fmaf(y.z, s.z, bb.z) + x.z, 0.0f);
        r.w = fmaxf(fmaf(y.w, s.w, bb.w) + x.w, 0.0f);
        op[i] = r;
    }
}

extern "C" void kernel_launch(void* const* d_in, const int* in_sizes, int n_in,
                              void* d_out, int out_size) {
    const float* x0        = (const float*)d_in[0];
    const float* fm        = (const float*)d_in[1];
    const float* W         = (const float*)d_in[2];
    const float* b         = (const float*)d_in[3];
    const float* gamma     = (const float*)d_in[4];
    const float* beta      = (const float*)d_in[5];
    const int*   shift_in  = (const int*)d_in[6];
    const int*   shift_out = (const int*)d_in[7];
    float* out = (float*)d_out;

    const int smem1 = Dd * YSTR * 4 + Cc * Dd * 4 + VC * 8 + VC * 2;  // 71040 B
    cudaFuncSetAttribute(k1, cudaFuncAttributeMaxDynamicSharedMemorySize, smem1);

    kprep<<<(NSLOT * VD + 255) / 256, 256>>>(fm, shift_in, shift_out);
    k1<<<NT / TT1, 256, smem1>>>(x0, W, b);
    k3<<<(VD + 255) / 256, 256>>>(gamma, beta, shift_out);
    k4<<<Nn * Dd, 256>>>(x0, out);
}